// round 1
// baseline (speedup 1.0000x reference)
#include <cuda_runtime.h>
#include <cuda_bf16.h>
#include <math.h>

#define NN    100000
#define NPAD  100096      // 391 * 256
#define EE    1250000
#define RR    16
#define DD    64

// ---------------- static device scratch (no allocs allowed) ----------------
__device__ __nv_bfloat16 g_egoB[NPAD * DD];   // ego in bf16, zero-padded rows
__device__ __nv_bfloat16 g_Wt[RR * DD * DD];  // W transposed: Wt[r][j][d] = W[r][d][j]
__device__ float         g_T[NPAD * DD];      // per-relation transformed (L2-resident)
__device__ float         g_exps[EE];          // exp(score) per edge
__device__ int           g_eid[EE];           // CSR edge ids
__device__ int           g_rowstart[NN + 1];
__device__ int           g_cursor[NN];
__device__ int           g_cnt[NN];

// ---------------- init: convert ego->bf16 (pad 0), transpose W, zero counts ----------------
__global__ void k_init(const float* __restrict__ ego, const float* __restrict__ W, int N) {
    int idx = blockIdx.x * blockDim.x + threadIdx.x;
    if (idx < NPAD * DD)
        g_egoB[idx] = __float2bfloat16(idx < N * DD ? ego[idx] : 0.0f);
    if (idx < RR * DD * DD) {
        int r = idx >> 12, rem = idx & 4095;
        int j = rem >> 6, d = rem & 63;
        g_Wt[idx] = __float2bfloat16(W[(r << 12) + d * DD + j]);
    }
    if (idx < N) g_cnt[idx] = 0;
}

// ---------------- CSR build ----------------
__global__ void k_hist(const int* __restrict__ head, int E) {
    int e = blockIdx.x * blockDim.x + threadIdx.x;
    if (e < E) atomicAdd(&g_cnt[head[e]], 1);
}

__global__ void k_scan(int N, int E) {
    __shared__ int carry;
    __shared__ int warp_sums[32];
    int tid = threadIdx.x;
    if (tid == 0) carry = 0;
    __syncthreads();
    for (int base = 0; base < N; base += 1024) {
        int i = base + tid;
        int v = (i < N) ? g_cnt[i] : 0;
        int x = v;
        #pragma unroll
        for (int o = 1; o < 32; o <<= 1) {
            int y = __shfl_up_sync(0xffffffffu, x, o);
            if ((tid & 31) >= o) x += y;
        }
        if ((tid & 31) == 31) warp_sums[tid >> 5] = x;
        __syncthreads();
        if (tid < 32) {
            int s = warp_sums[tid];
            int xs = s;
            #pragma unroll
            for (int o = 1; o < 32; o <<= 1) {
                int y = __shfl_up_sync(0xffffffffu, xs, o);
                if (tid >= o) xs += y;
            }
            warp_sums[tid] = xs - s;    // exclusive
        }
        __syncthreads();
        int excl = (x - v) + warp_sums[tid >> 5] + carry;
        if (i < N) { g_rowstart[i] = excl; g_cursor[i] = excl; }
        __syncthreads();
        if (tid == 1023) carry = excl + v;
        __syncthreads();
    }
    if (tid == 0) g_rowstart[N] = E;
}

__global__ void k_fill(const int* __restrict__ head, int E) {
    int e = blockIdx.x * blockDim.x + threadIdx.x;
    if (e < E) {
        int pos = atomicAdd(&g_cursor[head[e]], 1);
        g_eid[pos] = e;
    }
}

// ---------------- GEMM: T = egoB @ W[r]  (bf16 mma.sync, fp32 accum) ----------------
// Block = 256 threads = 8 warps; warp does 32 rows x 64 cols; tiles m16n8k16.
__global__ void __launch_bounds__(256) k_gemm(int r) {
    int warp = threadIdx.x >> 5, lane = threadIdx.x & 31;
    int g = lane >> 2, t = lane & 3;
    int base = blockIdx.x * 256 + warp * 32;
    const __nv_bfloat16* Wr = g_Wt + (r << 12);

    float acc[2][8][4];
    #pragma unroll
    for (int i = 0; i < 2; i++)
        #pragma unroll
        for (int j = 0; j < 8; j++)
            #pragma unroll
            for (int q = 0; q < 4; q++) acc[i][j][q] = 0.0f;

    #pragma unroll
    for (int ks = 0; ks < 4; ks++) {
        int k0 = ks * 16;
        unsigned a[2][4];
        #pragma unroll
        for (int mt = 0; mt < 2; mt++) {
            int r0 = base + mt * 16;
            const unsigned* p0 = (const unsigned*)(g_egoB + (size_t)(r0 + g) * DD + k0 + 2 * t);
            const unsigned* p1 = (const unsigned*)(g_egoB + (size_t)(r0 + g + 8) * DD + k0 + 2 * t);
            a[mt][0] = p0[0];
            a[mt][1] = p1[0];
            a[mt][2] = p0[4];   // +8 bf16 in k
            a[mt][3] = p1[4];
        }
        #pragma unroll
        for (int nt = 0; nt < 8; nt++) {
            const unsigned* q = (const unsigned*)(Wr + (nt * 8 + g) * DD + k0 + 2 * t);
            unsigned b0 = q[0], b1 = q[4];
            #pragma unroll
            for (int mt = 0; mt < 2; mt++) {
                asm volatile(
                    "mma.sync.aligned.m16n8k16.row.col.f32.bf16.bf16.f32 "
                    "{%0,%1,%2,%3}, {%4,%5,%6,%7}, {%8,%9}, {%0,%1,%2,%3};"
                    : "+f"(acc[mt][nt][0]), "+f"(acc[mt][nt][1]),
                      "+f"(acc[mt][nt][2]), "+f"(acc[mt][nt][3])
                    : "r"(a[mt][0]), "r"(a[mt][1]), "r"(a[mt][2]), "r"(a[mt][3]),
                      "r"(b0), "r"(b1));
            }
        }
    }
    #pragma unroll
    for (int mt = 0; mt < 2; mt++)
        #pragma unroll
        for (int nt = 0; nt < 8; nt++) {
            int row0 = base + mt * 16 + g;
            int col = nt * 8 + 2 * t;
            *(float2*)&g_T[(size_t)row0 * DD + col]       = make_float2(acc[mt][nt][0], acc[mt][nt][1]);
            *(float2*)&g_T[(size_t)(row0 + 8) * DD + col] = make_float2(acc[mt][nt][2], acc[mt][nt][3]);
        }
}

// ---------------- score pass for relation r ----------------
__global__ void k_score(const int* __restrict__ head, const int* __restrict__ tail,
                        const int* __restrict__ etype, const float* __restrict__ ego,
                        int E, int r) {
    int lane = threadIdx.x & 31;
    int wbase = blockIdx.x * blockDim.x + threadIdx.x - lane;
    int e = wbase + lane;
    int ty = (e < E) ? etype[e] : -1;
    bool m = (ty == r);
    int h_l = 0, tl_l = 0;
    if (m) { h_l = head[e]; tl_l = tail[e]; }
    unsigned mask = __ballot_sync(0xffffffffu, m);
    while (mask) {
        int j = __ffs(mask) - 1;
        mask &= mask - 1;
        int h  = __shfl_sync(0xffffffffu, h_l, j);
        int tl = __shfl_sync(0xffffffffu, tl_l, j);
        float2 a = *(const float2*)&g_T[(size_t)h * DD + 2 * lane];
        float2 b = *(const float2*)&ego[(size_t)tl * DD + 2 * lane];
        float p = a.x * b.x + a.y * b.y;
        #pragma unroll
        for (int o = 16; o; o >>= 1) p += __shfl_xor_sync(0xffffffffu, p, o);
        if (lane == j) {
            float s = p < 0.0f ? 0.01f * p : p;
            g_exps[wbase + j] = __expf(s);
        }
    }
}

// ---------------- aggregation: warp per node, CSR, no atomics ----------------
__global__ void k_agg(const int* __restrict__ tail, const float* __restrict__ ego,
                      float* __restrict__ out, int N) {
    int w = (blockIdx.x * blockDim.x + threadIdx.x) >> 5;
    int lane = threadIdx.x & 31;
    if (w >= N) return;
    int s = g_rowstart[w], en = g_rowstart[w + 1];
    int cnt = en - s;
    float ax = 0.0f, ay = 0.0f, denom = 0.0f;
    for (int i = s; i < en; ++i) {
        int e = g_eid[i];
        float es = g_exps[e];
        int tl = tail[e];
        float2 v = *(const float2*)&ego[(size_t)tl * DD + 2 * lane];
        ax += es * v.x;
        ay += es * v.y;
        denom += es;
    }
    float sc = cnt > 0 ? 1.0f / (denom * (float)cnt) : 0.0f;
    *(float2*)&out[(size_t)w * DD + 2 * lane] = make_float2(ax * sc, ay * sc);
}

// ---------------- launch ----------------
extern "C" void kernel_launch(void* const* d_in, const int* in_sizes, int n_in,
                              void* d_out, int out_size) {
    const float* ego   = (const float*)d_in[0];
    const float* W     = (const float*)d_in[1];
    const int*   eidx  = (const int*)d_in[2];
    const int*   etype = (const int*)d_in[3];
    int N = in_sizes[0] / DD;
    int E = in_sizes[3];
    const int* head = eidx;
    const int* tail = eidx + E;
    float* out = (float*)d_out;

    k_init<<<(NPAD * DD + 255) / 256, 256>>>(ego, W, N);
    k_hist<<<(E + 255) / 256, 256>>>(head, E);
    k_scan<<<1, 1024>>>(N, E);
    k_fill<<<(E + 255) / 256, 256>>>(head, E);
    for (int r = 0; r < RR; r++) {
        k_gemm<<<NPAD / 256, 256>>>(r);
        k_score<<<(E + 255) / 256, 256>>>(head, tail, etype, ego, E, r);
    }
    k_agg<<<(N * 32 + 255) / 256, 256>>>(tail, ego, out, N);
}

// round 2
// speedup vs baseline: 1.4202x; 1.4202x over previous
#include <cuda_runtime.h>
#include <cuda_bf16.h>
#include <math.h>

#define NN    100000
#define NPAD  100096      // 391 * 256
#define EE    1250000
#define RR    16
#define DD    64
#define SCANB (NPAD / 256)   // 391

// ---------------- static device scratch (no allocs allowed) ----------------
__device__ __nv_bfloat16 g_egoB[NPAD * DD];            // ego bf16, zero-padded
__device__ __nv_bfloat16 g_Wbf[RR * DD * DD];          // Wt[r][j][d] = W[r][d][j]
__device__ __nv_bfloat16 g_Tall[(size_t)RR * NPAD * DD]; // all-relation transform, bf16
__device__ float         g_exps[EE];
__device__ int           g_eid[EE];
__device__ int           g_rowstart[NN + 2];
__device__ int           g_cursor[NN];
__device__ int           g_cnt[NN];
__device__ int           g_bsum[SCANB + 1];
__device__ int           g_boff[SCANB + 1];

// ---------------- init ----------------
__global__ void k_init(const float* __restrict__ ego, const float* __restrict__ W, int N) {
    int idx = blockIdx.x * blockDim.x + threadIdx.x;
    if (idx < NPAD * DD)
        g_egoB[idx] = __float2bfloat16(idx < N * DD ? ego[idx] : 0.0f);
    if (idx < RR * DD * DD) {
        int r = idx >> 12, rem = idx & 4095;
        int j = rem >> 6, d = rem & 63;
        g_Wbf[idx] = __float2bfloat16(W[(r << 12) + d * DD + j]);
    }
    if (idx < N) g_cnt[idx] = 0;
}

// ---------------- CSR build ----------------
__global__ void k_hist(const int* __restrict__ head, int E) {
    int e = blockIdx.x * blockDim.x + threadIdx.x;
    if (e < E) atomicAdd(&g_cnt[head[e]], 1);
}

// phase 1: per-block sums of g_cnt
__global__ void k_scan1(int N) {
    __shared__ int sh[8];
    int b = blockIdx.x, t = threadIdx.x;
    int i = b * 256 + t;
    int v = (i < N) ? g_cnt[i] : 0;
    int x = v;
    #pragma unroll
    for (int o = 16; o; o >>= 1) x += __shfl_xor_sync(0xffffffffu, x, o);
    if ((t & 31) == 0) sh[t >> 5] = x;
    __syncthreads();
    if (t == 0) {
        int s = 0;
        #pragma unroll
        for (int q = 0; q < 8; q++) s += sh[q];
        g_bsum[b] = s;
    }
}

// phase 2: exclusive scan of 391 block sums (one block, 512 threads)
__global__ void k_scan2() {
    __shared__ int wsum[16];
    int t = threadIdx.x;
    int v = (t < SCANB) ? g_bsum[t] : 0;
    int x = v;
    #pragma unroll
    for (int o = 1; o < 32; o <<= 1) {
        int y = __shfl_up_sync(0xffffffffu, x, o);
        if ((t & 31) >= o) x += y;
    }
    if ((t & 31) == 31) wsum[t >> 5] = x;
    __syncthreads();
    if (t < 16) {
        int s = wsum[t], xs = s;
        #pragma unroll
        for (int o = 1; o < 16; o <<= 1) {
            int y = __shfl_up_sync(0xffffu, xs, o);
            if (t >= o) xs += y;
        }
        wsum[t] = xs - s;
    }
    __syncthreads();
    if (t < SCANB) g_boff[t] = (x - v) + wsum[t >> 5];
}

// phase 3: intra-block exclusive scan + block offset -> rowstart, cursor
__global__ void k_scan3(int N, int E) {
    __shared__ int wsum[8];
    int b = blockIdx.x, t = threadIdx.x;
    int i = b * 256 + t;
    int v = (i < N) ? g_cnt[i] : 0;
    int x = v;
    #pragma unroll
    for (int o = 1; o < 32; o <<= 1) {
        int y = __shfl_up_sync(0xffffffffu, x, o);
        if ((t & 31) >= o) x += y;
    }
    if ((t & 31) == 31) wsum[t >> 5] = x;
    __syncthreads();
    if (t < 8) {
        int s = wsum[t], xs = s;
        #pragma unroll
        for (int o = 1; o < 8; o <<= 1) {
            int y = __shfl_up_sync(0xffu, xs, o);
            if (t >= o) xs += y;
        }
        wsum[t] = xs - s;
    }
    __syncthreads();
    int excl = (x - v) + wsum[t >> 5] + g_boff[b];
    if (i <= N) g_rowstart[i] = (i == N) ? E : excl;
    if (i < N)  g_cursor[i] = excl;
}

__global__ void k_fill(const int* __restrict__ head, int E) {
    int e = blockIdx.x * blockDim.x + threadIdx.x;
    if (e < E) {
        int pos = atomicAdd(&g_cursor[head[e]], 1);
        g_eid[pos] = e;
    }
}

// ---------------- GEMM: T_all[r] = egoB @ W[r], bf16 out ----------------
// grid (391, 16); block 256 = 8 warps; warp: 32 rows x 64 cols; m16n8k16.
__global__ void __launch_bounds__(256) k_gemm() {
    __shared__ __nv_bfloat16 sW[DD * DD];   // Wt[r] tile: [j][d]
    int r = blockIdx.y;
    int warp = threadIdx.x >> 5, lane = threadIdx.x & 31;
    int g = lane >> 2, t = lane & 3;
    int base = blockIdx.x * 256 + warp * 32;

    // stage W[r] (8KB) into smem
    const float4* src = (const float4*)(g_Wbf + (r << 12));
    float4* dst = (float4*)sW;
    for (int i = threadIdx.x; i < DD * DD / 8; i += 256) dst[i] = src[i];
    __syncthreads();

    float acc[2][8][4];
    #pragma unroll
    for (int i = 0; i < 2; i++)
        #pragma unroll
        for (int j = 0; j < 8; j++)
            #pragma unroll
            for (int q = 0; q < 4; q++) acc[i][j][q] = 0.0f;

    #pragma unroll
    for (int ks = 0; ks < 4; ks++) {
        int k0 = ks * 16;
        unsigned a[2][4];
        #pragma unroll
        for (int mt = 0; mt < 2; mt++) {
            int r0 = base + mt * 16;
            const unsigned* p0 = (const unsigned*)(g_egoB + (size_t)(r0 + g) * DD + k0 + 2 * t);
            const unsigned* p1 = (const unsigned*)(g_egoB + (size_t)(r0 + g + 8) * DD + k0 + 2 * t);
            a[mt][0] = p0[0];
            a[mt][1] = p1[0];
            a[mt][2] = p0[4];
            a[mt][3] = p1[4];
        }
        #pragma unroll
        for (int nt = 0; nt < 8; nt++) {
            const unsigned* q = (const unsigned*)(sW + (nt * 8 + g) * DD + k0 + 2 * t);
            unsigned b0 = q[0], b1 = q[4];
            #pragma unroll
            for (int mt = 0; mt < 2; mt++) {
                asm volatile(
                    "mma.sync.aligned.m16n8k16.row.col.f32.bf16.bf16.f32 "
                    "{%0,%1,%2,%3}, {%4,%5,%6,%7}, {%8,%9}, {%0,%1,%2,%3};"
                    : "+f"(acc[mt][nt][0]), "+f"(acc[mt][nt][1]),
                      "+f"(acc[mt][nt][2]), "+f"(acc[mt][nt][3])
                    : "r"(a[mt][0]), "r"(a[mt][1]), "r"(a[mt][2]), "r"(a[mt][3]),
                      "r"(b0), "r"(b1));
            }
        }
    }
    __nv_bfloat16* T = g_Tall + (size_t)r * NPAD * DD;
    #pragma unroll
    for (int mt = 0; mt < 2; mt++)
        #pragma unroll
        for (int nt = 0; nt < 8; nt++) {
            int row0 = base + mt * 16 + g;
            int col = nt * 8 + 2 * t;
            __nv_bfloat162 h0 = __floats2bfloat162_rn(acc[mt][nt][0], acc[mt][nt][1]);
            __nv_bfloat162 h1 = __floats2bfloat162_rn(acc[mt][nt][2], acc[mt][nt][3]);
            *(unsigned*)(T + (size_t)row0 * DD + col)       = *(unsigned*)&h0;
            *(unsigned*)(T + (size_t)(row0 + 8) * DD + col) = *(unsigned*)&h1;
        }
}

// ---------------- single score pass: warp handles 2 edges ----------------
__global__ void k_score(const int* __restrict__ head, const int* __restrict__ tail,
                        const int* __restrict__ etype, const float* __restrict__ ego,
                        int E) {
    int lane = threadIdx.x & 31;
    int w = (blockIdx.x * blockDim.x + threadIdx.x) >> 5;
    int e0 = w * 2;
    float p[2] = {0.0f, 0.0f};
    #pragma unroll
    for (int q = 0; q < 2; q++) {
        int e = e0 + q;
        if (e < E) {
            int h = head[e], tl = tail[e], r = etype[e];
            __nv_bfloat162 tv = *(const __nv_bfloat162*)
                (g_Tall + ((size_t)r * NPAD + h) * DD + 2 * lane);
            float2 a = __bfloat1622float2(tv);
            float2 b = *(const float2*)(ego + (size_t)tl * DD + 2 * lane);
            p[q] = fmaf(a.x, b.x, a.y * b.y);
        }
    }
    #pragma unroll
    for (int o = 16; o; o >>= 1) {
        p[0] += __shfl_xor_sync(0xffffffffu, p[0], o);
        p[1] += __shfl_xor_sync(0xffffffffu, p[1], o);
    }
    if (lane < 2 && e0 + lane < E) {
        float s = p[lane];
        s = s < 0.0f ? 0.01f * s : s;
        g_exps[e0 + lane] = __expf(s);
    }
}

// ---------------- aggregation: warp per node, batched loads ----------------
__global__ void k_agg(const int* __restrict__ tail, const float* __restrict__ ego,
                      float* __restrict__ out, int N) {
    int w = (blockIdx.x * blockDim.x + threadIdx.x) >> 5;
    int lane = threadIdx.x & 31;
    if (w >= N) return;
    int s = g_rowstart[w], en = g_rowstart[w + 1];
    int cnt = en - s;
    float ax = 0.0f, ay = 0.0f, dsum = 0.0f;
    for (int base = s; base < en; base += 32) {
        int nchunk = min(32, en - base);
        float ex = 0.0f;
        int tl = 0;
        if (lane < nchunk) {
            int e = g_eid[base + lane];
            ex = g_exps[e];
            tl = tail[e];
        }
        dsum += ex;
        for (int j = 0; j < nchunk; j++) {
            int   tj  = __shfl_sync(0xffffffffu, tl, j);
            float exj = __shfl_sync(0xffffffffu, ex, j);
            float2 v = *(const float2*)(ego + (size_t)tj * DD + 2 * lane);
            ax = fmaf(exj, v.x, ax);
            ay = fmaf(exj, v.y, ay);
        }
    }
    #pragma unroll
    for (int o = 16; o; o >>= 1) dsum += __shfl_xor_sync(0xffffffffu, dsum, o);
    float sc = cnt > 0 ? 1.0f / (dsum * (float)cnt) : 0.0f;
    *(float2*)&out[(size_t)w * DD + 2 * lane] = make_float2(ax * sc, ay * sc);
}

// ---------------- launch ----------------
extern "C" void kernel_launch(void* const* d_in, const int* in_sizes, int n_in,
                              void* d_out, int out_size) {
    const float* ego   = (const float*)d_in[0];
    const float* W     = (const float*)d_in[1];
    const int*   eidx  = (const int*)d_in[2];
    const int*   etype = (const int*)d_in[3];
    int N = in_sizes[0] / DD;
    int E = in_sizes[3];
    const int* head = eidx;
    const int* tail = eidx + E;
    float* out = (float*)d_out;

    k_init<<<(NPAD * DD + 255) / 256, 256>>>(ego, W, N);
    k_hist<<<(E + 255) / 256, 256>>>(head, E);
    k_scan1<<<SCANB, 256>>>(N);
    k_scan2<<<1, 512>>>();
    k_scan3<<<SCANB, 256>>>(N, E);
    k_fill<<<(E + 255) / 256, 256>>>(head, E);
    k_gemm<<<dim3(NPAD / 256, RR), 256>>>();
    k_score<<<(E + 15) / 16, 256>>>(head, tail, etype, ego, E);
    k_agg<<<(N * 32 + 255) / 256, 256>>>(tail, ego, out, N);
}

// round 3
// speedup vs baseline: 1.8589x; 1.3089x over previous
#include <cuda_runtime.h>
#include <cuda_bf16.h>
#include <math.h>

#define NN    100000
#define NPAD  100096      // 391 * 256
#define EE    1250000
#define RR    16
#define DD    64
#define SCANB (NPAD / 256)   // 391

// ---------------- static device scratch (no allocs allowed) ----------------
__device__ __nv_bfloat16 g_egoB[NPAD * DD];              // ego bf16, zero-padded
__device__ __nv_bfloat16 g_Wbf[RR * DD * DD];            // Wt[r][j][d] = W[r][d][j]
__device__ __nv_bfloat16 g_Tall[(size_t)RR * NPAD * DD]; // all-relation transform, bf16
__device__ int2          g_pair[EE];                     // CSR-ordered (tail, etype)
__device__ int           g_rowstart[NN + 2];
__device__ int           g_cursor[NN];
__device__ int           g_cnt[NN];
__device__ int           g_bsum[SCANB + 1];
__device__ int           g_boff[SCANB + 1];

// ---------------- init ----------------
__global__ void k_init(const float* __restrict__ ego, const float* __restrict__ W, int N) {
    int idx = blockIdx.x * blockDim.x + threadIdx.x;
    if (idx < NPAD * DD)
        g_egoB[idx] = __float2bfloat16(idx < N * DD ? ego[idx] : 0.0f);
    if (idx < RR * DD * DD) {
        int r = idx >> 12, rem = idx & 4095;
        int j = rem >> 6, d = rem & 63;
        g_Wbf[idx] = __float2bfloat16(W[(r << 12) + d * DD + j]);
    }
    if (idx < N) g_cnt[idx] = 0;
}

// ---------------- CSR build ----------------
__global__ void k_hist(const int* __restrict__ head, int E) {
    int e = blockIdx.x * blockDim.x + threadIdx.x;
    if (e < E) atomicAdd(&g_cnt[head[e]], 1);
}

__global__ void k_scan1(int N) {
    __shared__ int sh[8];
    int b = blockIdx.x, t = threadIdx.x;
    int i = b * 256 + t;
    int v = (i < N) ? g_cnt[i] : 0;
    int x = v;
    #pragma unroll
    for (int o = 16; o; o >>= 1) x += __shfl_xor_sync(0xffffffffu, x, o);
    if ((t & 31) == 0) sh[t >> 5] = x;
    __syncthreads();
    if (t == 0) {
        int s = 0;
        #pragma unroll
        for (int q = 0; q < 8; q++) s += sh[q];
        g_bsum[b] = s;
    }
}

__global__ void k_scan2() {
    __shared__ int wsum[16];
    int t = threadIdx.x;
    int v = (t < SCANB) ? g_bsum[t] : 0;
    int x = v;
    #pragma unroll
    for (int o = 1; o < 32; o <<= 1) {
        int y = __shfl_up_sync(0xffffffffu, x, o);
        if ((t & 31) >= o) x += y;
    }
    if ((t & 31) == 31) wsum[t >> 5] = x;
    __syncthreads();
    if (t < 16) {
        int s = wsum[t], xs = s;
        #pragma unroll
        for (int o = 1; o < 16; o <<= 1) {
            int y = __shfl_up_sync(0xffffu, xs, o);
            if (t >= o) xs += y;
        }
        wsum[t] = xs - s;
    }
    __syncthreads();
    if (t < SCANB) g_boff[t] = (x - v) + wsum[t >> 5];
}

__global__ void k_scan3(int N, int E) {
    __shared__ int wsum[8];
    int b = blockIdx.x, t = threadIdx.x;
    int i = b * 256 + t;
    int v = (i < N) ? g_cnt[i] : 0;
    int x = v;
    #pragma unroll
    for (int o = 1; o < 32; o <<= 1) {
        int y = __shfl_up_sync(0xffffffffu, x, o);
        if ((t & 31) >= o) x += y;
    }
    if ((t & 31) == 31) wsum[t >> 5] = x;
    __syncthreads();
    if (t < 8) {
        int s = wsum[t], xs = s;
        #pragma unroll
        for (int o = 1; o < 8; o <<= 1) {
            int y = __shfl_up_sync(0xffu, xs, o);
            if (t >= o) xs += y;
        }
        wsum[t] = xs - s;
    }
    __syncthreads();
    int excl = (x - v) + wsum[t >> 5] + g_boff[b];
    if (i <= N) g_rowstart[i] = (i == N) ? E : excl;
    if (i < N)  g_cursor[i] = excl;
}

// fill CSR slots with packed (tail, etype) so the fused pass streams them
__global__ void k_fill(const int* __restrict__ head, const int* __restrict__ tail,
                       const int* __restrict__ etype, int E) {
    int e = blockIdx.x * blockDim.x + threadIdx.x;
    if (e < E) {
        int pos = atomicAdd(&g_cursor[head[e]], 1);
        g_pair[pos] = make_int2(tail[e], etype[e]);
    }
}

// ---------------- GEMM: T_all[r] = egoB @ W[r], bf16 out ----------------
__global__ void __launch_bounds__(256) k_gemm() {
    __shared__ __nv_bfloat16 sW[DD * DD];
    int r = blockIdx.y;
    int warp = threadIdx.x >> 5, lane = threadIdx.x & 31;
    int g = lane >> 2, t = lane & 3;
    int base = blockIdx.x * 256 + warp * 32;

    const float4* src = (const float4*)(g_Wbf + (r << 12));
    float4* dst = (float4*)sW;
    for (int i = threadIdx.x; i < DD * DD / 8; i += 256) dst[i] = src[i];
    __syncthreads();

    float acc[2][8][4];
    #pragma unroll
    for (int i = 0; i < 2; i++)
        #pragma unroll
        for (int j = 0; j < 8; j++)
            #pragma unroll
            for (int q = 0; q < 4; q++) acc[i][j][q] = 0.0f;

    #pragma unroll
    for (int ks = 0; ks < 4; ks++) {
        int k0 = ks * 16;
        unsigned a[2][4];
        #pragma unroll
        for (int mt = 0; mt < 2; mt++) {
            int r0 = base + mt * 16;
            const unsigned* p0 = (const unsigned*)(g_egoB + (size_t)(r0 + g) * DD + k0 + 2 * t);
            const unsigned* p1 = (const unsigned*)(g_egoB + (size_t)(r0 + g + 8) * DD + k0 + 2 * t);
            a[mt][0] = p0[0];
            a[mt][1] = p1[0];
            a[mt][2] = p0[4];
            a[mt][3] = p1[4];
        }
        #pragma unroll
        for (int nt = 0; nt < 8; nt++) {
            const unsigned* q = (const unsigned*)(sW + (nt * 8 + g) * DD + k0 + 2 * t);
            unsigned b0 = q[0], b1 = q[4];
            #pragma unroll
            for (int mt = 0; mt < 2; mt++) {
                asm volatile(
                    "mma.sync.aligned.m16n8k16.row.col.f32.bf16.bf16.f32 "
                    "{%0,%1,%2,%3}, {%4,%5,%6,%7}, {%8,%9}, {%0,%1,%2,%3};"
                    : "+f"(acc[mt][nt][0]), "+f"(acc[mt][nt][1]),
                      "+f"(acc[mt][nt][2]), "+f"(acc[mt][nt][3])
                    : "r"(a[mt][0]), "r"(a[mt][1]), "r"(a[mt][2]), "r"(a[mt][3]),
                      "r"(b0), "r"(b1));
            }
        }
    }
    __nv_bfloat16* T = g_Tall + (size_t)r * NPAD * DD;
    #pragma unroll
    for (int mt = 0; mt < 2; mt++)
        #pragma unroll
        for (int nt = 0; nt < 8; nt++) {
            int row0 = base + mt * 16 + g;
            int col = nt * 8 + 2 * t;
            __nv_bfloat162 h0 = __floats2bfloat162_rn(acc[mt][nt][0], acc[mt][nt][1]);
            __nv_bfloat162 h1 = __floats2bfloat162_rn(acc[mt][nt][2], acc[mt][nt][3]);
            *(unsigned*)(T + (size_t)row0 * DD + col)       = *(unsigned*)&h0;
            *(unsigned*)(T + (size_t)(row0 + 8) * DD + col) = *(unsigned*)&h1;
        }
}

// ---------------- fused score + softmax + aggregate: warp per node ----------------
__global__ void __launch_bounds__(256) k_fused(const float* __restrict__ ego,
                                               float* __restrict__ out, int N) {
    int w = (blockIdx.x * blockDim.x + threadIdx.x) >> 5;
    int lane = threadIdx.x & 31;
    if (w >= N) return;
    int s = g_rowstart[w], en = g_rowstart[w + 1];
    int cnt = en - s;

    float ax = 0.0f, ay = 0.0f, den = 0.0f;
    const __nv_bfloat16* Trow = g_Tall + (size_t)w * DD + 2 * lane;  // + r*NPAD*DD

    int i = s;
    // 2-edge pipelined main loop
    for (; i + 1 < en; i += 2) {
        int2 pe0 = g_pair[i];
        int2 pe1 = g_pair[i + 1];
        __nv_bfloat162 t0 = *(const __nv_bfloat162*)(Trow + (size_t)pe0.y * NPAD * DD);
        __nv_bfloat162 t1 = *(const __nv_bfloat162*)(Trow + (size_t)pe1.y * NPAD * DD);
        float2 v0 = *(const float2*)(ego + (size_t)pe0.x * DD + 2 * lane);
        float2 v1 = *(const float2*)(ego + (size_t)pe1.x * DD + 2 * lane);
        float2 a0 = __bfloat1622float2(t0);
        float2 a1 = __bfloat1622float2(t1);
        float d0 = fmaf(a0.x, v0.x, a0.y * v0.y);
        float d1 = fmaf(a1.x, v1.x, a1.y * v1.y);
        #pragma unroll
        for (int o = 16; o; o >>= 1) {
            d0 += __shfl_xor_sync(0xffffffffu, d0, o);
            d1 += __shfl_xor_sync(0xffffffffu, d1, o);
        }
        float s0 = d0 < 0.0f ? 0.01f * d0 : d0;
        float s1 = d1 < 0.0f ? 0.01f * d1 : d1;
        float e0 = __expf(s0);
        float e1 = __expf(s1);
        ax = fmaf(e0, v0.x, ax);
        ay = fmaf(e0, v0.y, ay);
        ax = fmaf(e1, v1.x, ax);
        ay = fmaf(e1, v1.y, ay);
        den += e0 + e1;
    }
    if (i < en) {
        int2 pe = g_pair[i];
        __nv_bfloat162 t0 = *(const __nv_bfloat162*)(Trow + (size_t)pe.y * NPAD * DD);
        float2 v0 = *(const float2*)(ego + (size_t)pe.x * DD + 2 * lane);
        float2 a0 = __bfloat1622float2(t0);
        float d0 = fmaf(a0.x, v0.x, a0.y * v0.y);
        #pragma unroll
        for (int o = 16; o; o >>= 1) d0 += __shfl_xor_sync(0xffffffffu, d0, o);
        float s0 = d0 < 0.0f ? 0.01f * d0 : d0;
        float e0 = __expf(s0);
        ax = fmaf(e0, v0.x, ax);
        ay = fmaf(e0, v0.y, ay);
        den += e0;
    }

    float sc = cnt > 0 ? 1.0f / (den * (float)cnt) : 0.0f;
    *(float2*)&out[(size_t)w * DD + 2 * lane] = make_float2(ax * sc, ay * sc);
}

// ---------------- launch ----------------
extern "C" void kernel_launch(void* const* d_in, const int* in_sizes, int n_in,
                              void* d_out, int out_size) {
    const float* ego   = (const float*)d_in[0];
    const float* W     = (const float*)d_in[1];
    const int*   eidx  = (const int*)d_in[2];
    const int*   etype = (const int*)d_in[3];
    int N = in_sizes[0] / DD;
    int E = in_sizes[3];
    const int* head = eidx;
    const int* tail = eidx + E;
    float* out = (float*)d_out;

    k_init<<<(NPAD * DD + 255) / 256, 256>>>(ego, W, N);
    k_hist<<<(E + 255) / 256, 256>>>(head, E);
    k_scan1<<<SCANB, 256>>>(N);
    k_scan2<<<1, 512>>>();
    k_scan3<<<SCANB, 256>>>(N, E);
    k_fill<<<(E + 255) / 256, 256>>>(head, tail, etype, E);
    k_gemm<<<dim3(NPAD / 256, RR), 256>>>();
    k_fused<<<(N * 32 + 255) / 256, 256>>>(ego, out, N);
}